// round 15
// baseline (speedup 1.0000x reference)
#include <cuda_runtime.h>
#include <cstdint>
#include <math.h>

#define T    2048
#define HD   1024
#define ID   2048
#define NE   8

// ---------------- scratch (__device__ globals; no allocation allowed) ----------------
__device__ float g_H [(size_t)NE * T * ID];   // routed h = silu(g)*u
__device__ float g_SH[(size_t)T * ID];        // shared h
__device__ int   g_tok[NE * T];
__device__ float g_wt [NE * T];
__device__ int   g_cnt[NE];
__device__ float g_sump[NE];
__device__ float g_lse2[1];

// ---------------- small kernels ----------------
__global__ void k_reset() {
    int i = threadIdx.x;
    if (i < NE) { g_cnt[i] = 0; g_sump[i] = 0.f; }
    if (i == 0) g_lse2[0] = 0.f;
}

__global__ void k_router(const float* __restrict__ x, const float* __restrict__ rw) {
    int t = blockIdx.x, tid = threadIdx.x;
    float acc[NE];
#pragma unroll
    for (int e = 0; e < NE; e++) acc[e] = 0.f;
    const float* xr = x + (size_t)t * HD;
    for (int j = tid; j < HD; j += 128) {
        float xv = xr[j];
        const float* r = rw + (size_t)j * NE;
#pragma unroll
        for (int e = 0; e < NE; e++) acc[e] += xv * r[e];
    }
    __shared__ float sm[NE][128];
#pragma unroll
    for (int e = 0; e < NE; e++) sm[e][tid] = acc[e];
    __syncthreads();
    for (int s = 64; s > 0; s >>= 1) {
        if (tid < s)
#pragma unroll
            for (int e = 0; e < NE; e++) sm[e][tid] += sm[e][tid + s];
        __syncthreads();
    }
    if (tid == 0) {
        float l[NE];
#pragma unroll
        for (int e = 0; e < NE; e++) l[e] = sm[e][0];
        float m = l[0];
#pragma unroll
        for (int e = 1; e < NE; e++) m = fmaxf(m, l[e]);
        float p[NE], sum = 0.f;
#pragma unroll
        for (int e = 0; e < NE; e++) { p[e] = expf(l[e] - m); sum += p[e]; }
        float inv = 1.f / sum;
#pragma unroll
        for (int e = 0; e < NE; e++) p[e] *= inv;
        float lse = m + logf(sum);
        atomicAdd(&g_lse2[0], lse * lse);
#pragma unroll
        for (int e = 0; e < NE; e++) atomicAdd(&g_sump[e], p[e]);
        int i0 = 0;
#pragma unroll
        for (int e = 1; e < NE; e++) if (p[e] > p[i0]) i0 = e;
        int i1 = -1;
#pragma unroll
        for (int e = 0; e < NE; e++) {
            if (e == i0) continue;
            if (i1 < 0 || p[e] > p[i1]) i1 = e;
        }
        float w0 = p[i0], w1 = p[i1], s2 = 1.f / (p[i0] + p[i1]);
        w0 *= s2; w1 *= s2;
        int q0 = atomicAdd(&g_cnt[i0], 1);
        g_tok[i0 * T + q0] = t; g_wt[i0 * T + q0] = w0;
        int q1 = atomicAdd(&g_cnt[i1], 1);
        g_tok[i1 * T + q1] = t; g_wt[i1 * T + q1] = w1;
    }
}

__global__ void k_aux(float* __restrict__ out) {
    float fp = 0.f;
#pragma unroll
    for (int e = 0; e < NE; e++)
        fp += ((float)g_cnt[e] / (float)(T * 2)) * (g_sump[e] / (float)T);
    out[0] = 0.01f * (float)NE * fp + 0.001f * (g_lse2[0] / (float)T);
}

// ---------------- tf32 tensor-core GEMM helpers ----------------
__device__ __forceinline__ uint32_t to_tf32(float f) {
    uint32_t r; asm("cvt.rna.tf32.f32 %0, %1;" : "=r"(r) : "f"(f)); return r;
}

#define MMA_TF32(d, a, b)                                                      \
    asm volatile(                                                              \
        "mma.sync.aligned.m16n8k8.row.col.f32.tf32.tf32.f32 "                  \
        "{%0,%1,%2,%3},{%4,%5,%6,%7},{%8,%9},{%0,%1,%2,%3};"                   \
        : "+f"((d)[0]), "+f"((d)[1]), "+f"((d)[2]), "+f"((d)[3])               \
        : "r"((a)[0]), "r"((a)[1]), "r"((a)[2]), "r"((a)[3]),                  \
          "r"((b)[0]), "r"((b)[1]))

// A: Asm[row*36 + k] (conflict-free frag banks 4*grp+tg)
// B: Bsm[k*136 + n]  (conflict-free frag banks 8*tg+grp)
#define A_W   4608    // 128*36
#define A_W2  9216    // 256*36
#define B_W   4352    // 32*136

// ---- merged fused gate+up: z=0..7 routed (gather), z=8 shared ----
// 256 threads, 8 warps in 2(M)x4(N) grid, warp tile 64x32, block 128x128, BK=32.
__global__ __launch_bounds__(256, 1)
void k_gu(const float* __restrict__ x,
          const float* __restrict__ eg, const float* __restrict__ eu,
          const float* __restrict__ sg, const float* __restrict__ su,
          float* __restrict__ H, float* __restrict__ SH,
          const int* __restrict__ cnt, const int* __restrict__ tokall) {
    extern __shared__ uint32_t smem[];
    uint32_t* Asm  = smem;                 // 2 * A_W
    uint32_t* Bsm  = smem + 2 * A_W;       // 2 * B_W
    uint32_t* B2sm = smem + 2 * A_W + 2 * B_W;

    int e = blockIdx.z;
    bool routed = (e < NE);
    int M = routed ? cnt[e] : T;
    int m0 = blockIdx.x * 128;
    if (m0 >= M) return;
    int n0 = blockIdx.y * 128;

    const float* Bp  = routed ? eg + (size_t)e * HD * ID : sg;
    const float* B2p = routed ? eu + (size_t)e * HD * ID : su;
    float* Cp = routed ? H + (size_t)e * T * ID : SH;
    const int* toks = routed ? tokall + e * T : nullptr;

    int tid = threadIdx.x;
    int lane = tid & 31, wid = tid >> 5;
    int wm = wid & 1;        // 2 x 64 rows
    int wn = wid >> 1;       // 4 x 32 cols
    int grp = lane >> 2, tg = lane & 3;

    // producers: A 128x32 (16 vals/thread), B,B2 32x128 (16 vals/thread each)
    int aRow = tid >> 1, aks = (tid & 1) * 16;
    int sRow;
    {
        int s = m0 + aRow; s = (s < M) ? s : (M - 1);
        sRow = routed ? toks[s] : s;
    }
    const float* aPtr = x + (size_t)sRow * HD + aks;
    int bK = tid >> 3, bN = (tid & 7) * 16;
    const float* bPtr  = Bp  + (size_t)bK * ID + n0 + bN;
    const float* b2Ptr = B2p + (size_t)bK * ID + n0 + bN;
    uint32_t aw = aRow * 36 + aks;
    uint32_t bw = bK * 136 + bN;

    float accg[4][4][4], accu[4][4][4];
#pragma unroll
    for (int i = 0; i < 4; i++)
#pragma unroll
        for (int j = 0; j < 4; j++)
#pragma unroll
            for (int k = 0; k < 4; k++) { accg[i][j][k] = 0.f; accu[i][j][k] = 0.f; }

    const int nslabs = HD / 32;
    float4 la[4], lb[4], lc[4];
#define LOAD_SLAB(kt)                                                          \
    do {                                                                       \
        const float* _a = aPtr + (kt) * 32;                                    \
        la[0] = ((const float4*)_a)[0]; la[1] = ((const float4*)_a)[1];        \
        la[2] = ((const float4*)_a)[2]; la[3] = ((const float4*)_a)[3];        \
        const float* _b = bPtr + (size_t)(kt) * 32 * ID;                       \
        lb[0] = ((const float4*)_b)[0]; lb[1] = ((const float4*)_b)[1];        \
        lb[2] = ((const float4*)_b)[2]; lb[3] = ((const float4*)_b)[3];        \
        const float* _c = b2Ptr + (size_t)(kt) * 32 * ID;                      \
        lc[0] = ((const float4*)_c)[0]; lc[1] = ((const float4*)_c)[1];        \
        lc[2] = ((const float4*)_c)[2]; lc[3] = ((const float4*)_c)[3];        \
    } while (0)
#define STS_SLAB(bf)                                                           \
    do {                                                                       \
        uint32_t* d = &Asm[(bf) * A_W + aw];                                   \
        _Pragma("unroll")                                                      \
        for (int j = 0; j < 4; j++) {                                          \
            uint4 v = { to_tf32(la[j].x), to_tf32(la[j].y),                    \
                        to_tf32(la[j].z), to_tf32(la[j].w) };                  \
            *(uint4*)(d + 4 * j) = v;                                          \
        }                                                                      \
        uint32_t* g = &Bsm[(bf) * B_W + bw];                                   \
        _Pragma("unroll")                                                      \
        for (int j = 0; j < 4; j++) {                                          \
            uint4 v = { to_tf32(lb[j].x), to_tf32(lb[j].y),                    \
                        to_tf32(lb[j].z), to_tf32(lb[j].w) };                  \
            *(uint4*)(g + 4 * j) = v;                                          \
        }                                                                      \
        uint32_t* u = &B2sm[(bf) * B_W + bw];                                  \
        _Pragma("unroll")                                                      \
        for (int j = 0; j < 4; j++) {                                          \
            uint4 v = { to_tf32(lc[j].x), to_tf32(lc[j].y),                    \
                        to_tf32(lc[j].z), to_tf32(lc[j].w) };                  \
            *(uint4*)(u + 4 * j) = v;                                          \
        }                                                                      \
    } while (0)

    LOAD_SLAB(0);
    int buf = 0;
    STS_SLAB(0);
    __syncthreads();

    for (int kt = 0; kt < nslabs; kt++) {
        bool has = (kt + 1 < nslabs);
        if (has) LOAD_SLAB(kt + 1);
        uint32_t aofs = buf * A_W, bofs = buf * B_W;
#pragma unroll
        for (int kk = 0; kk < 32; kk += 8) {
            uint32_t a[4][4], bg[4][2], bu[4][2];
#pragma unroll
            for (int mt = 0; mt < 4; mt++) {
                uint32_t r0 = aofs + (wm * 64 + mt * 16 + grp) * 36;
                a[mt][0] = Asm[r0 + kk + tg];
                a[mt][1] = Asm[r0 + 288 + kk + tg];
                a[mt][2] = Asm[r0 + kk + tg + 4];
                a[mt][3] = Asm[r0 + 288 + kk + tg + 4];
            }
#pragma unroll
            for (int nt = 0; nt < 4; nt++) {
                int c = wn * 32 + nt * 8 + grp;
                bg[nt][0] = Bsm[bofs + (kk + tg) * 136 + c];
                bg[nt][1] = Bsm[bofs + (kk + 4 + tg) * 136 + c];
                bu[nt][0] = B2sm[bofs + (kk + tg) * 136 + c];
                bu[nt][1] = B2sm[bofs + (kk + 4 + tg) * 136 + c];
            }
#pragma unroll
            for (int mt = 0; mt < 4; mt++)
#pragma unroll
                for (int nt = 0; nt < 4; nt++) {
                    MMA_TF32(accg[mt][nt], a[mt], bg[nt]);
                    MMA_TF32(accu[mt][nt], a[mt], bu[nt]);
                }
        }
        if (has) {
            buf ^= 1;
            STS_SLAB(buf);
            __syncthreads();
        }
    }

#pragma unroll
    for (int mt = 0; mt < 4; mt++) {
        int rbase = m0 + wm * 64 + mt * 16 + grp;
#pragma unroll
        for (int half = 0; half < 2; half++) {
            int r = rbase + half * 8;
            if (r < M) {
                float* dst = Cp + (size_t)r * ID;
#pragma unroll
                for (int nt = 0; nt < 4; nt++) {
                    int c = n0 + wn * 32 + nt * 8 + tg * 2;
#pragma unroll
                    for (int j = 0; j < 2; j++) {
                        float gv = accg[mt][nt][half * 2 + j];
                        float uv = accu[mt][nt][half * 2 + j];
                        dst[c + j] = gv * uv / (1.f + __expf(-gv));
                    }
                }
            }
        }
    }
#undef LOAD_SLAB
#undef STS_SLAB
}

// ---- merged down-proj: z=0..7 routed (weighted scatter), z=8 shared ----
// 512 threads, 16 warps in 4(M)x4(N) grid, warp tile 64x32, block 256x128, BK=32.
__global__ __launch_bounds__(512, 1)
void k_down(const float* __restrict__ H, const float* __restrict__ SH,
            const float* __restrict__ ed, const float* __restrict__ sd,
            float* __restrict__ out,
            const int* __restrict__ cnt, const int* __restrict__ tokall,
            const float* __restrict__ wtall) {
    extern __shared__ uint32_t smem[];
    uint32_t* Asm = smem;               // 2 * A_W2
    uint32_t* Bsm = smem + 2 * A_W2;    // 2 * B_W

    int e = blockIdx.z;
    bool routed = (e < NE);
    int M = routed ? cnt[e] : T;
    int m0 = blockIdx.x * 256;
    if (m0 >= M) return;
    int n0 = blockIdx.y * 128;

    const float* Ap = routed ? H + (size_t)e * T * ID : SH;
    const float* Bp = routed ? ed + (size_t)e * ID * HD : sd;
    const int*   toks = routed ? tokall + e * T : nullptr;
    const float* wts  = routed ? wtall  + e * T : nullptr;

    int tid = threadIdx.x;
    int lane = tid & 31, wid = tid >> 5;
    int wm = wid & 3;        // 4 x 64 rows
    int wn = wid >> 2;       // 4 x 32 cols
    int grp = lane >> 2, tg = lane & 3;

    // producers: A 256x32 (16 vals/thread), B 32x128 (8 vals/thread)
    int aRow = tid >> 1, aks = (tid & 1) * 16;
    int sRow = m0 + aRow; sRow = (sRow < M) ? sRow : (M - 1);
    const float* aPtr = Ap + (size_t)sRow * ID + aks;
    int bK = tid >> 4, bN = (tid & 15) * 8;
    const float* bPtr = Bp + (size_t)bK * HD + n0 + bN;
    uint32_t aw = aRow * 36 + aks;
    uint32_t bw = bK * 136 + bN;

    float accg[4][4][4];
#pragma unroll
    for (int i = 0; i < 4; i++)
#pragma unroll
        for (int j = 0; j < 4; j++)
#pragma unroll
            for (int k = 0; k < 4; k++) accg[i][j][k] = 0.f;

    const int nslabs = ID / 32;
    float4 la[4], lb[2];
#define LOAD_SLAB(kt)                                                          \
    do {                                                                       \
        const float* _a = aPtr + (kt) * 32;                                    \
        la[0] = ((const float4*)_a)[0]; la[1] = ((const float4*)_a)[1];        \
        la[2] = ((const float4*)_a)[2]; la[3] = ((const float4*)_a)[3];        \
        const float* _b = bPtr + (size_t)(kt) * 32 * HD;                       \
        lb[0] = ((const float4*)_b)[0]; lb[1] = ((const float4*)_b)[1];        \
    } while (0)
#define STS_SLAB(bf)                                                           \
    do {                                                                       \
        uint32_t* d = &Asm[(bf) * A_W2 + aw];                                  \
        _Pragma("unroll")                                                      \
        for (int j = 0; j < 4; j++) {                                          \
            uint4 v = { to_tf32(la[j].x), to_tf32(la[j].y),                    \
                        to_tf32(la[j].z), to_tf32(la[j].w) };                  \
            *(uint4*)(d + 4 * j) = v;                                          \
        }                                                                      \
        uint32_t* g = &Bsm[(bf) * B_W + bw];                                   \
        _Pragma("unroll")                                                      \
        for (int j = 0; j < 2; j++) {                                          \
            uint4 v = { to_tf32(lb[j].x), to_tf32(lb[j].y),                    \
                        to_tf32(lb[j].z), to_tf32(lb[j].w) };                  \
            *(uint4*)(g + 4 * j) = v;                                          \
        }                                                                      \
    } while (0)

    LOAD_SLAB(0);
    int buf = 0;
    STS_SLAB(0);
    __syncthreads();

    for (int kt = 0; kt < nslabs; kt++) {
        bool has = (kt + 1 < nslabs);
        if (has) LOAD_SLAB(kt + 1);
        uint32_t aofs = buf * A_W2, bofs = buf * B_W;
#pragma unroll
        for (int kk = 0; kk < 32; kk += 8) {
            uint32_t a[4][4], bg[4][2];
#pragma unroll
            for (int mt = 0; mt < 4; mt++) {
                uint32_t r0 = aofs + (wm * 64 + mt * 16 + grp) * 36;
                a[mt][0] = Asm[r0 + kk + tg];
                a[mt][1] = Asm[r0 + 288 + kk + tg];
                a[mt][2] = Asm[r0 + kk + tg + 4];
                a[mt][3] = Asm[r0 + 288 + kk + tg + 4];
            }
#pragma unroll
            for (int nt = 0; nt < 4; nt++) {
                int c = wn * 32 + nt * 8 + grp;
                bg[nt][0] = Bsm[bofs + (kk + tg) * 136 + c];
                bg[nt][1] = Bsm[bofs + (kk + 4 + tg) * 136 + c];
            }
#pragma unroll
            for (int mt = 0; mt < 4; mt++)
#pragma unroll
                for (int nt = 0; nt < 4; nt++)
                    MMA_TF32(accg[mt][nt], a[mt], bg[nt]);
        }
        if (has) {
            buf ^= 1;
            STS_SLAB(buf);
            __syncthreads();
        }
    }

#pragma unroll
    for (int mt = 0; mt < 4; mt++) {
        int rbase = m0 + wm * 64 + mt * 16 + grp;
#pragma unroll
        for (int half = 0; half < 2; half++) {
            int r = rbase + half * 8;
            if (r < M) {
                int tok; float w;
                if (routed) { tok = toks[r]; w = wts[r]; }
                else        { tok = r;       w = 1.f; }
                float* dst = out + (size_t)tok * HD;
#pragma unroll
                for (int nt = 0; nt < 4; nt++) {
                    int c = n0 + wn * 32 + nt * 8 + tg * 2;
                    atomicAdd(dst + c,     w * accg[mt][nt][half * 2 + 0]);
                    atomicAdd(dst + c + 1, w * accg[mt][nt][half * 2 + 1]);
                }
            }
        }
    }
#undef LOAD_SLAB
#undef STS_SLAB
}

// ---------------- launch ----------------
extern "C" void kernel_launch(void* const* d_in, const int* in_sizes, int n_in,
                              void* d_out, int out_size) {
    const float* x  = (const float*)d_in[0];
    const float* rw = (const float*)d_in[1];
    const float* eg = (const float*)d_in[2];
    const float* eu = (const float*)d_in[3];
    const float* ed = (const float*)d_in[4];
    const float* sg = (const float*)d_in[5];
    const float* su = (const float*)d_in[6];
    const float* sd = (const float*)d_in[7];
    float* out = (float*)d_out;

    float *pH, *pSH, *pwt;
    int *ptok, *pcnt;
    cudaGetSymbolAddress((void**)&pH,   g_H);
    cudaGetSymbolAddress((void**)&pSH,  g_SH);
    cudaGetSymbolAddress((void**)&ptok, g_tok);
    cudaGetSymbolAddress((void**)&pwt,  g_wt);
    cudaGetSymbolAddress((void**)&pcnt, g_cnt);
    (void)in_sizes; (void)n_in;

    const int SM_GU   = (2 * A_W  + 4 * B_W) * 4;  // 106496 B
    const int SM_DOWN = (2 * A_W2 + 2 * B_W) * 4;  // 108544 B
    cudaFuncSetAttribute(k_gu,   cudaFuncAttributeMaxDynamicSharedMemorySize, SM_GU);
    cudaFuncSetAttribute(k_down, cudaFuncAttributeMaxDynamicSharedMemorySize, SM_DOWN);

    k_reset<<<1, 32>>>();
    cudaMemsetAsync(out, 0, (size_t)T * HD * sizeof(float));
    k_router<<<T, 128>>>(x, rw);
    if (out_size > T * HD) k_aux<<<1, 1>>>(out + (size_t)T * HD);

    // merged fused gate+up (routed z=0..7 + shared z=8) -> h buffers
    k_gu<<<dim3(T / 128, ID / 128, NE + 1), 256, SM_GU>>>(
        x, eg, eu, sg, su, pH, pSH, pcnt, ptok);

    // merged down-proj (routed weighted scatter z=0..7 + shared z=8) -> out
    k_down<<<dim3(T / 256, HD / 128, NE + 1), 512, SM_DOWN>>>(
        pH, pSH, ed, sd, out, pcnt, ptok, pwt);
}

// round 17
// speedup vs baseline: 1.2378x; 1.2378x over previous
#include <cuda_runtime.h>
#include <cstdint>
#include <math.h>

#define T    2048
#define HD   1024
#define ID   2048
#define NE   8

// ---------------- scratch (__device__ globals; no allocation allowed) ----------------
__device__ float g_H [(size_t)NE * T * ID];   // routed h = silu(g)*u
__device__ float g_SH[(size_t)T * ID];        // shared h
__device__ int   g_tok[NE * T];
__device__ float g_wt [NE * T];
__device__ int   g_cnt[NE];
__device__ float g_sump[NE];
__device__ float g_lse2[1];
__device__ int   g_tix[2];                    // persistent-scheduler counters

// ---------------- small kernels ----------------
__global__ void k_reset() {
    int i = threadIdx.x;
    if (i < NE) { g_cnt[i] = 0; g_sump[i] = 0.f; }
    if (i == 0) { g_lse2[0] = 0.f; g_tix[0] = 0; g_tix[1] = 0; }
}

__global__ void k_router(const float* __restrict__ x, const float* __restrict__ rw) {
    int t = blockIdx.x, tid = threadIdx.x;
    float acc[NE];
#pragma unroll
    for (int e = 0; e < NE; e++) acc[e] = 0.f;
    const float* xr = x + (size_t)t * HD;
    for (int j = tid; j < HD; j += 128) {
        float xv = xr[j];
        const float* r = rw + (size_t)j * NE;
#pragma unroll
        for (int e = 0; e < NE; e++) acc[e] += xv * r[e];
    }
    __shared__ float sm[NE][128];
#pragma unroll
    for (int e = 0; e < NE; e++) sm[e][tid] = acc[e];
    __syncthreads();
    for (int s = 64; s > 0; s >>= 1) {
        if (tid < s)
#pragma unroll
            for (int e = 0; e < NE; e++) sm[e][tid] += sm[e][tid + s];
        __syncthreads();
    }
    if (tid == 0) {
        float l[NE];
#pragma unroll
        for (int e = 0; e < NE; e++) l[e] = sm[e][0];
        float m = l[0];
#pragma unroll
        for (int e = 1; e < NE; e++) m = fmaxf(m, l[e]);
        float p[NE], sum = 0.f;
#pragma unroll
        for (int e = 0; e < NE; e++) { p[e] = expf(l[e] - m); sum += p[e]; }
        float inv = 1.f / sum;
#pragma unroll
        for (int e = 0; e < NE; e++) p[e] *= inv;
        float lse = m + logf(sum);
        atomicAdd(&g_lse2[0], lse * lse);
#pragma unroll
        for (int e = 0; e < NE; e++) atomicAdd(&g_sump[e], p[e]);
        int i0 = 0;
#pragma unroll
        for (int e = 1; e < NE; e++) if (p[e] > p[i0]) i0 = e;
        int i1 = -1;
#pragma unroll
        for (int e = 0; e < NE; e++) {
            if (e == i0) continue;
            if (i1 < 0 || p[e] > p[i1]) i1 = e;
        }
        float w0 = p[i0], w1 = p[i1], s2 = 1.f / (p[i0] + p[i1]);
        w0 *= s2; w1 *= s2;
        int q0 = atomicAdd(&g_cnt[i0], 1);
        g_tok[i0 * T + q0] = t; g_wt[i0 * T + q0] = w0;
        int q1 = atomicAdd(&g_cnt[i1], 1);
        g_tok[i1 * T + q1] = t; g_wt[i1 * T + q1] = w1;
    }
}

__global__ void k_aux(float* __restrict__ out) {
    float fp = 0.f;
#pragma unroll
    for (int e = 0; e < NE; e++)
        fp += ((float)g_cnt[e] / (float)(T * 2)) * (g_sump[e] / (float)T);
    out[0] = 0.01f * (float)NE * fp + 0.001f * (g_lse2[0] / (float)T);
}

// ---------------- tf32 tensor-core GEMM (proven R13/691 core) ----------------
__device__ __forceinline__ uint32_t to_tf32(float f) {
    uint32_t r; asm("cvt.rna.tf32.f32 %0, %1;" : "=r"(r) : "f"(f)); return r;
}

#define MMA_TF32(d, a, b)                                                      \
    asm volatile(                                                              \
        "mma.sync.aligned.m16n8k8.row.col.f32.tf32.tf32.f32 "                  \
        "{%0,%1,%2,%3},{%4,%5,%6,%7},{%8,%9},{%0,%1,%2,%3};"                   \
        : "+f"((d)[0]), "+f"((d)[1]), "+f"((d)[2]), "+f"((d)[3])               \
        : "r"((a)[0]), "r"((a)[1]), "r"((a)[2]), "r"((a)[3]),                  \
          "r"((b)[0]), "r"((b)[1]))

// A: Asm[row*36 + k] (conflict-free frag banks 4*grp+tg)
// B: Bsm[k*136 + n]  (conflict-free frag banks 8*tg+grp)
#define A_W 4608    // 128*36
#define B_W 4352    // 32*136

#define NCTA 152    // GB300 SM count; persistent CTAs

// ---- persistent merged fused gate+up: z=0..7 routed (gather), z=8 shared ----
// 512 threads, 16 warps 4x4, warp tile 32x32, block 128x128, BK=32.
__global__ __launch_bounds__(512, 1)
void k_gu(const float* __restrict__ x,
          const float* __restrict__ eg, const float* __restrict__ eu,
          const float* __restrict__ sg, const float* __restrict__ su,
          float* __restrict__ H, float* __restrict__ SH,
          const int* __restrict__ cnt, const int* __restrict__ tokall) {
    extern __shared__ uint32_t smem[];
    uint32_t* Asm  = smem;                 // 2 * A_W
    uint32_t* Bsm  = smem + 2 * A_W;       // 2 * B_W
    uint32_t* B2sm = smem + 2 * A_W + 2 * B_W;
    __shared__ int s_t;

    int tid = threadIdx.x;
    int lane = tid & 31, wid = tid >> 5;
    int wm = wid & 3, wn = wid >> 2;
    int grp = lane >> 2, tg = lane & 3;
    int aRow = tid >> 2, aOff = (tid & 3) * 8;
    int bK = tid >> 4, bN = (tid & 15) * 8;
    uint32_t aw = aRow * 36 + aOff;
    uint32_t bw = bK * 136 + bN;

    const int NT = (NE + 1) * 16 * 16;     // z * x * y

    for (;;) {
        __syncthreads();                   // protect smem + s_t across tiles
        if (tid == 0) s_t = atomicAdd(&g_tix[0], 1);
        __syncthreads();
        int t = s_t;
        if (t >= NT) return;
        int z = t >> 8, xb = (t >> 4) & 15, yb = t & 15;
        bool routed = (z < NE);
        int M = routed ? cnt[z] : T;
        int m0 = xb * 128;
        if (m0 >= M) continue;
        int n0 = yb * 128;

        const float* Bp  = routed ? eg + (size_t)z * HD * ID : sg;
        const float* B2p = routed ? eu + (size_t)z * HD * ID : su;
        float* Cp = routed ? H + (size_t)z * T * ID : SH;
        const int* toks = routed ? tokall + z * T : nullptr;

        int sRow;
        {
            int s = m0 + aRow; s = (s < M) ? s : (M - 1);
            sRow = routed ? toks[s] : s;
        }
        const float* aPtr  = x   + (size_t)sRow * HD + aOff;
        const float* bPtr  = Bp  + (size_t)bK * ID + n0 + bN;
        const float* b2Ptr = B2p + (size_t)bK * ID + n0 + bN;

        float accg[2][4][4], accu[2][4][4];
#pragma unroll
        for (int i = 0; i < 2; i++)
#pragma unroll
            for (int j = 0; j < 4; j++)
#pragma unroll
                for (int k = 0; k < 4; k++) { accg[i][j][k] = 0.f; accu[i][j][k] = 0.f; }

        const int nslabs = HD / 32;
        float4 a0, a1, b0, b1, c0, c1;
#define LOAD_SLAB(kt)                                                          \
    do {                                                                       \
        const float* _a = aPtr + (kt) * 32;                                    \
        a0 = *(const float4*)_a; a1 = *(const float4*)(_a + 4);                \
        const float* _b = bPtr + (size_t)(kt) * 32 * ID;                       \
        b0 = *(const float4*)_b; b1 = *(const float4*)(_b + 4);                \
        const float* _c = b2Ptr + (size_t)(kt) * 32 * ID;                      \
        c0 = *(const float4*)_c; c1 = *(const float4*)(_c + 4);                \
    } while (0)
#define STS_SLAB(bf)                                                           \
    do {                                                                       \
        uint32_t* d = &Asm[(bf) * A_W + aw];                                   \
        d[0]=to_tf32(a0.x); d[1]=to_tf32(a0.y); d[2]=to_tf32(a0.z); d[3]=to_tf32(a0.w); \
        d[4]=to_tf32(a1.x); d[5]=to_tf32(a1.y); d[6]=to_tf32(a1.z); d[7]=to_tf32(a1.w); \
        uint32_t* g = &Bsm[(bf) * B_W + bw];                                   \
        g[0]=to_tf32(b0.x); g[1]=to_tf32(b0.y); g[2]=to_tf32(b0.z); g[3]=to_tf32(b0.w); \
        g[4]=to_tf32(b1.x); g[5]=to_tf32(b1.y); g[6]=to_tf32(b1.z); g[7]=to_tf32(b1.w); \
        uint32_t* u = &B2sm[(bf) * B_W + bw];                                  \
        u[0]=to_tf32(c0.x); u[1]=to_tf32(c0.y); u[2]=to_tf32(c0.z); u[3]=to_tf32(c0.w); \
        u[4]=to_tf32(c1.x); u[5]=to_tf32(c1.y); u[6]=to_tf32(c1.z); u[7]=to_tf32(c1.w); \
    } while (0)

        LOAD_SLAB(0);
        int buf = 0;
        STS_SLAB(0);
        __syncthreads();

        for (int kt = 0; kt < nslabs; kt++) {
            bool has = (kt + 1 < nslabs);
            if (has) LOAD_SLAB(kt + 1);
            uint32_t aofs = buf * A_W, bofs = buf * B_W;
#pragma unroll
            for (int kk = 0; kk < 32; kk += 8) {
                uint32_t a[2][4], bg[4][2], bu[4][2];
#pragma unroll
                for (int mt = 0; mt < 2; mt++) {
                    uint32_t r0 = aofs + (wm * 32 + mt * 16 + grp) * 36;
                    a[mt][0] = Asm[r0 + kk + tg];
                    a[mt][1] = Asm[r0 + 288 + kk + tg];
                    a[mt][2] = Asm[r0 + kk + tg + 4];
                    a[mt][3] = Asm[r0 + 288 + kk + tg + 4];
                }
#pragma unroll
                for (int nt = 0; nt < 4; nt++) {
                    int c = wn * 32 + nt * 8 + grp;
                    bg[nt][0] = Bsm[bofs + (kk + tg) * 136 + c];
                    bg[nt][1] = Bsm[bofs + (kk + 4 + tg) * 136 + c];
                    bu[nt][0] = B2sm[bofs + (kk + tg) * 136 + c];
                    bu[nt][1] = B2sm[bofs + (kk + 4 + tg) * 136 + c];
                }
#pragma unroll
                for (int mt = 0; mt < 2; mt++)
#pragma unroll
                    for (int nt = 0; nt < 4; nt++) {
                        MMA_TF32(accg[mt][nt], a[mt], bg[nt]);
                        MMA_TF32(accu[mt][nt], a[mt], bu[nt]);
                    }
            }
            if (has) {
                buf ^= 1;
                STS_SLAB(buf);
                __syncthreads();
            }
        }

#pragma unroll
        for (int mt = 0; mt < 2; mt++) {
            int rbase = m0 + wm * 32 + mt * 16 + grp;
#pragma unroll
            for (int half = 0; half < 2; half++) {
                int r = rbase + half * 8;
                if (r < M) {
                    float* dst = Cp + (size_t)r * ID;
#pragma unroll
                    for (int nt = 0; nt < 4; nt++) {
                        int c = n0 + wn * 32 + nt * 8 + tg * 2;
#pragma unroll
                        for (int j = 0; j < 2; j++) {
                            float gv = accg[mt][nt][half * 2 + j];
                            float uv = accu[mt][nt][half * 2 + j];
                            dst[c + j] = gv * uv / (1.f + __expf(-gv));
                        }
                    }
                }
            }
        }
#undef LOAD_SLAB
#undef STS_SLAB
    }
}

// ---- persistent merged down-proj: z=0..7 routed (weighted scatter), z=8 shared ----
// 512 threads, 16 warps 4x4, warp tile 32x32, block 128x128, BK=32.
__global__ __launch_bounds__(512, 1)
void k_down(const float* __restrict__ H, const float* __restrict__ SH,
            const float* __restrict__ ed, const float* __restrict__ sd,
            float* __restrict__ out,
            const int* __restrict__ cnt, const int* __restrict__ tokall,
            const float* __restrict__ wtall) {
    extern __shared__ uint32_t smem[];
    uint32_t* Asm = smem;              // 2 * A_W
    uint32_t* Bsm = smem + 2 * A_W;    // 2 * B_W
    __shared__ int s_t;

    int tid = threadIdx.x;
    int lane = tid & 31, wid = tid >> 5;
    int wm = wid & 3, wn = wid >> 2;
    int grp = lane >> 2, tg = lane & 3;
    int aRow = tid >> 2, aOff = (tid & 3) * 8;
    int bK = tid >> 4, bN = (tid & 15) * 8;
    uint32_t aw = aRow * 36 + aOff;
    uint32_t bw = bK * 136 + bN;

    const int NT = (NE + 1) * 16 * 8;   // z * x(16) * y(8)

    for (;;) {
        __syncthreads();
        if (tid == 0) s_t = atomicAdd(&g_tix[1], 1);
        __syncthreads();
        int t = s_t;
        if (t >= NT) return;
        int z = t >> 7, xb = (t >> 3) & 15, yb = t & 7;
        bool routed = (z < NE);
        int M = routed ? cnt[z] : T;
        int m0 = xb * 128;
        if (m0 >= M) continue;
        int n0 = yb * 128;

        const float* Ap = routed ? H + (size_t)z * T * ID : SH;
        const float* Bp = routed ? ed + (size_t)z * ID * HD : sd;
        const int*   toks = routed ? tokall + z * T : nullptr;
        const float* wts  = routed ? wtall  + z * T : nullptr;

        int sRow = m0 + aRow; sRow = (sRow < M) ? sRow : (M - 1);
        const float* aPtr = Ap + (size_t)sRow * ID + aOff;
        const float* bPtr = Bp + (size_t)bK * HD + n0 + bN;

        float accg[2][4][4];
#pragma unroll
        for (int i = 0; i < 2; i++)
#pragma unroll
            for (int j = 0; j < 4; j++)
#pragma unroll
                for (int k = 0; k < 4; k++) accg[i][j][k] = 0.f;

        const int nslabs = ID / 32;
        float4 a0, a1, b0, b1;
#define LOAD_SLAB(kt)                                                          \
    do {                                                                       \
        const float* _a = aPtr + (kt) * 32;                                    \
        a0 = *(const float4*)_a; a1 = *(const float4*)(_a + 4);                \
        const float* _b = bPtr + (size_t)(kt) * 32 * HD;                       \
        b0 = *(const float4*)_b; b1 = *(const float4*)(_b + 4);                \
    } while (0)
#define STS_SLAB(bf)                                                           \
    do {                                                                       \
        uint32_t* d = &Asm[(bf) * A_W + aw];                                   \
        d[0]=to_tf32(a0.x); d[1]=to_tf32(a0.y); d[2]=to_tf32(a0.z); d[3]=to_tf32(a0.w); \
        d[4]=to_tf32(a1.x); d[5]=to_tf32(a1.y); d[6]=to_tf32(a1.z); d[7]=to_tf32(a1.w); \
        uint32_t* g = &Bsm[(bf) * B_W + bw];                                   \
        g[0]=to_tf32(b0.x); g[1]=to_tf32(b0.y); g[2]=to_tf32(b0.z); g[3]=to_tf32(b0.w); \
        g[4]=to_tf32(b1.x); g[5]=to_tf32(b1.y); g[6]=to_tf32(b1.z); g[7]=to_tf32(b1.w); \
    } while (0)

        LOAD_SLAB(0);
        int buf = 0;
        STS_SLAB(0);
        __syncthreads();

        for (int kt = 0; kt < nslabs; kt++) {
            bool has = (kt + 1 < nslabs);
            if (has) LOAD_SLAB(kt + 1);
            uint32_t aofs = buf * A_W, bofs = buf * B_W;
#pragma unroll
            for (int kk = 0; kk < 32; kk += 8) {
                uint32_t a[2][4], bg[4][2];
#pragma unroll
                for (int mt = 0; mt < 2; mt++) {
                    uint32_t r0 = aofs + (wm * 32 + mt * 16 + grp) * 36;
                    a[mt][0] = Asm[r0 + kk + tg];
                    a[mt][1] = Asm[r0 + 288 + kk + tg];
                    a[mt][2] = Asm[r0 + kk + tg + 4];
                    a[mt][3] = Asm[r0 + 288 + kk + tg + 4];
                }
#pragma unroll
                for (int nt = 0; nt < 4; nt++) {
                    int c = wn * 32 + nt * 8 + grp;
                    bg[nt][0] = Bsm[bofs + (kk + tg) * 136 + c];
                    bg[nt][1] = Bsm[bofs + (kk + 4 + tg) * 136 + c];
                }
#pragma unroll
                for (int mt = 0; mt < 2; mt++)
#pragma unroll
                    for (int nt = 0; nt < 4; nt++)
                        MMA_TF32(accg[mt][nt], a[mt], bg[nt]);
            }
            if (has) {
                buf ^= 1;
                STS_SLAB(buf);
                __syncthreads();
            }
        }

#pragma unroll
        for (int mt = 0; mt < 2; mt++) {
            int rbase = m0 + wm * 32 + mt * 16 + grp;
#pragma unroll
            for (int half = 0; half < 2; half++) {
                int r = rbase + half * 8;
                if (r < M) {
                    int tok; float w;
                    if (routed) { tok = toks[r]; w = wts[r]; }
                    else        { tok = r;       w = 1.f; }
                    float* dst = out + (size_t)tok * HD;
#pragma unroll
                    for (int nt = 0; nt < 4; nt++) {
                        int c = n0 + wn * 32 + nt * 8 + tg * 2;
                        atomicAdd(dst + c,     w * accg[mt][nt][half * 2 + 0]);
                        atomicAdd(dst + c + 1, w * accg[mt][nt][half * 2 + 1]);
                    }
                }
            }
        }
#undef LOAD_SLAB
#undef STS_SLAB
    }
}

// ---------------- launch ----------------
extern "C" void kernel_launch(void* const* d_in, const int* in_sizes, int n_in,
                              void* d_out, int out_size) {
    const float* x  = (const float*)d_in[0];
    const float* rw = (const float*)d_in[1];
    const float* eg = (const float*)d_in[2];
    const float* eu = (const float*)d_in[3];
    const float* ed = (const float*)d_in[4];
    const float* sg = (const float*)d_in[5];
    const float* su = (const float*)d_in[6];
    const float* sd = (const float*)d_in[7];
    float* out = (float*)d_out;

    float *pH, *pSH, *pwt;
    int *ptok, *pcnt;
    cudaGetSymbolAddress((void**)&pH,   g_H);
    cudaGetSymbolAddress((void**)&pSH,  g_SH);
    cudaGetSymbolAddress((void**)&ptok, g_tok);
    cudaGetSymbolAddress((void**)&pwt,  g_wt);
    cudaGetSymbolAddress((void**)&pcnt, g_cnt);
    (void)in_sizes; (void)n_in;

    const int SM_GU   = (2 * A_W + 4 * B_W) * 4;  // 106496 B
    const int SM_DOWN = (2 * A_W + 2 * B_W) * 4;  //  71680 B
    cudaFuncSetAttribute(k_gu,   cudaFuncAttributeMaxDynamicSharedMemorySize, SM_GU);
    cudaFuncSetAttribute(k_down, cudaFuncAttributeMaxDynamicSharedMemorySize, SM_DOWN);

    k_reset<<<1, 32>>>();
    cudaMemsetAsync(out, 0, (size_t)T * HD * sizeof(float));
    k_router<<<T, 128>>>(x, rw);
    if (out_size > T * HD) k_aux<<<1, 1>>>(out + (size_t)T * HD);

    // persistent merged fused gate+up (routed z=0..7 + shared z=8) -> h buffers
    k_gu<<<NCTA, 512, SM_GU>>>(x, eg, eu, sg, su, pH, pSH, pcnt, ptok);

    // persistent merged down-proj (routed weighted scatter z=0..7 + shared z=8) -> out
    k_down<<<NCTA, 512, SM_DOWN>>>(pH, pSH, ed, sd, out, pcnt, ptok, pwt);
}